// round 6
// baseline (speedup 1.0000x reference)
#include <cuda_runtime.h>
#include <cuda_fp16.h>
#include <cstdint>

// ====================== helpers ======================
__device__ __forceinline__ uint32_t smem_u32(const void* p) {
    uint32_t a;
    asm("{ .reg .u64 t; cvta.to.shared.u64 t, %1; cvt.u32.u64 %0, t; }" : "=r"(a) : "l"(p));
    return a;
}
__device__ __forceinline__ void ldsm_x4t(uint32_t* d, uint32_t addr) {
    asm volatile("ldmatrix.sync.aligned.m8n8.x4.trans.shared.b16 {%0,%1,%2,%3}, [%4];"
        : "=r"(d[0]), "=r"(d[1]), "=r"(d[2]), "=r"(d[3]) : "r"(addr));
}
__device__ __forceinline__ void mma_f16(float* c, const uint32_t* a, uint32_t b0, uint32_t b1) {
    asm volatile(
        "mma.sync.aligned.m16n8k16.row.col.f32.f16.f16.f32 "
        "{%0,%1,%2,%3}, {%4,%5,%6,%7}, {%8,%9}, {%0,%1,%2,%3};"
        : "+f"(c[0]), "+f"(c[1]), "+f"(c[2]), "+f"(c[3])
        : "r"(a[0]), "r"(a[1]), "r"(a[2]), "r"(a[3]), "r"(b0), "r"(b1));
}
__device__ __forceinline__ uint32_t h2u(__half2 h) { return *reinterpret_cast<uint32_t*>(&h); }

// ====================== weight prep (once) ======================
// g_Bh: 128 rows (logical mma-k) x 64 fp16, 16B chunks XOR-swizzled by (k&7).
// Row k holds W[perm(k)][*]:  q=k&15, c=(q>>1)&3, e=q&1, hi8=q>>3 -> p = 16*(k>>4)+4c+2*hi8+e
__device__ unsigned char g_Bh[128 * 128];

__global__ void prep_weight_kernel(const float* __restrict__ weight) {
    int i = blockIdx.x * 256 + threadIdx.x;
    if (i < 8192) {
        int k = i >> 6, n = i & 63;
        int ks = k >> 4, q = k & 15;
        int c = (q >> 1) & 3, e = q & 1, hi8 = q >> 3;
        int p = 16 * ks + 4 * c + 2 * hi8 + e;
        __half h = __float2half_rn(weight[p * 64 + n]);
        int chunk = (n >> 3) ^ (k & 7);
        int off = k * 128 + chunk * 16 + (n & 7) * 2;
        *reinterpret_cast<__half*>(g_Bh + off) = h;
    }
}

// ====================== smem layout ======================
#define SM_B    0u
#define SM_W    16384u
#define SM_BIAS 18432u
#define SMEM_TOTAL 18688

__global__ void __launch_bounds__(128, 4) gcn_f16_kernel(
    const float* __restrict__ feat,
    const float* __restrict__ w,
    const float* __restrict__ bias,
    const float* __restrict__ alpha_p,
    float* __restrict__ out,
    int n_pool_blocks)
{
    extern __shared__ unsigned char s_raw[];
    const uint32_t sb = smem_u32(s_raw);
    const int tid = threadIdx.x;
    const int wid = tid >> 5;
    const int lid = tid & 31;

    const float alpha = __ldg(alpha_p);

    // ---------- stage B tile (16KB), edge weights (2KB), bias ----------
    {
        const uint4* gbp = (const uint4*)&g_Bh[0];
        uint4* sp = (uint4*)(s_raw + SM_B);
        #pragma unroll
        for (int i = 0; i < 8; ++i) sp[tid + i * 128] = gbp[tid + i * 128];
        ((uint4*)(s_raw + SM_W))[tid] =
            ((const uint4*)(w + (size_t)blockIdx.x * 512))[tid];
        if (tid < 16)  ((uint4*)(s_raw + SM_BIAS))[tid] = ((const uint4*)bias)[tid];
    }
    __syncthreads();

    // ---------- MMA: warp = 32 rows x 64 cols; K = 2x128 (hi,lo + both m16 tiles share B) ----------
    float acc[2][8][4];
    #pragma unroll
    for (int mt = 0; mt < 2; ++mt)
        #pragma unroll
        for (int t = 0; t < 8; ++t)
            #pragma unroll
            for (int i = 0; i < 4; ++i) acc[mt][t][i] = 0.f;

    {
        const int c  = lid & 3;
        const int rq = lid >> 2;
        const float* fbase = feat + (size_t)blockIdx.x * (128 * 128)
                           + (size_t)(wid * 32 + rq) * 128 + 4 * c;
        // row groups: mt*16 + {0,8}
        const float* f00 = fbase;                 // mt=0, +0
        const float* f01 = fbase + 8 * 128;       // mt=0, +8
        const float* f10 = fbase + 16 * 128;      // mt=1, +0
        const float* f11 = fbase + 24 * 128;      // mt=1, +8

        const int bKrel = (lid & 7) + ((lid >> 3) & 1) * 8;
        const uint32_t bRow = (uint32_t)bKrel * 128u;
        const int bS  = bKrel & 7;
        const int bC0 = lid >> 4;

        #pragma unroll
        for (int ks = 0; ks < 8; ++ks) {
            uint32_t b[16];
            const uint32_t bkb = sb + SM_B + (uint32_t)(ks * 2048) + bRow;
            #pragma unroll
            for (int j = 0; j < 4; ++j)
                ldsm_x4t(b + 4 * j, bkb + (uint32_t)((((j << 1) + bC0) ^ bS) << 4));

            #pragma unroll
            for (int mt = 0; mt < 2; ++mt) {
                float4 F0 = *(const float4*)((mt ? f10 : f00) + 16 * ks);
                float4 F1 = *(const float4*)((mt ? f11 : f01) + 16 * ks);

                __half2 H0 = __floats2half2_rn(F0.x, F0.y);
                __half2 H1 = __floats2half2_rn(F1.x, F1.y);
                __half2 H2 = __floats2half2_rn(F0.z, F0.w);
                __half2 H3 = __floats2half2_rn(F1.z, F1.w);
                float2 g0 = __half22float2(H0), g1 = __half22float2(H1);
                float2 g2 = __half22float2(H2), g3 = __half22float2(H3);
                __half2 L0 = __floats2half2_rn(F0.x - g0.x, F0.y - g0.y);
                __half2 L1 = __floats2half2_rn(F1.x - g1.x, F1.y - g1.y);
                __half2 L2 = __floats2half2_rn(F0.z - g2.x, F0.w - g2.y);
                __half2 L3 = __floats2half2_rn(F1.z - g3.x, F1.w - g3.y);
                uint32_t aH[4] = { h2u(H0), h2u(H1), h2u(H2), h2u(H3) };
                uint32_t aL[4] = { h2u(L0), h2u(L1), h2u(L2), h2u(L3) };

                #pragma unroll
                for (int ns = 0; ns < 8; ++ns) {
                    uint32_t b0 = b[(ns >> 1) * 4 + (ns & 1) * 2];
                    uint32_t b1 = b[(ns >> 1) * 4 + (ns & 1) * 2 + 1];
                    mma_f16(acc[mt][ns], aH, b0, b1);
                    mma_f16(acc[mt][ns], aL, b0, b1);
                }
            }
        }
    }

    // ---------- in-register epilogue ----------
    {
        const float* wsm = (const float*)(s_raw + SM_W);
        const float* bsm = (const float*)(s_raw + SM_BIAS);
        const int q  = lid & 3;
        const int i  = (lid >> 2) & 3;          // row within node-block
        const int bq = (lid >> 4) & 1;
        const int srcBase = lid & 0x13;         // keep q + bq bits

        #pragma unroll
        for (int mt = 0; mt < 2; ++mt) {
            #pragma unroll
            for (int h = 0; h < 2; ++h) {
                const int b_cta = wid * 8 + mt * 4 + 2 * h + bq;
                const float* wb = wsm + b_cta * 16;

                float v[16];
                #pragma unroll
                for (int ns = 0; ns < 8; ++ns) {
                    v[2 * ns]     = acc[mt][ns][2 * h];
                    v[2 * ns + 1] = acc[mt][ns][2 * h + 1];
                }

                float hp[16];
                #pragma unroll
                for (int ns = 0; ns < 8; ++ns) {
                    float2 bv = *(const float2*)(bsm + ns * 8 + q * 2);
                    hp[2 * ns] = bv.x; hp[2 * ns + 1] = bv.y;
                }
                #pragma unroll
                for (int s = 1; s <= 3; ++s) {
                    int sl = srcBase | (s << 2);
                    float wsj = wb[s * 4 + i];
                    #pragma unroll
                    for (int c = 0; c < 16; ++c)
                        hp[c] = fmaf(wsj, __shfl_sync(0xFFFFFFFFu, v[c], sl), hp[c]);
                }

                #pragma unroll
                for (int c = 0; c < 16; ++c)
                    hp[c] = (hp[c] >= 0.f) ? hp[c] : alpha * hp[c];
                #pragma unroll
                for (int c = 0; c < 16; ++c) hp[c] += __shfl_xor_sync(0xFFFFFFFFu, hp[c], 4);
                #pragma unroll
                for (int c = 0; c < 16; ++c) hp[c] += __shfl_xor_sync(0xFFFFFFFFu, hp[c], 8);

                float pn = 0.f, an = 0.f;
                #pragma unroll
                for (int c = 0; c < 16; ++c) {
                    float p = hp[c] * 0.25f;
                    hp[c] = p;
                    pn = fmaf(p, p, pn);
                    float2 bv = *(const float2*)(bsm + (c >> 1) * 8 + q * 2);
                    float x = v[c] + ((c & 1) ? bv.y : bv.x);
                    x = (x >= 0.f) ? x : alpha * x;
                    an = fmaf(x, x, an);
                }
                pn += __shfl_xor_sync(0xFFFFFFFFu, pn, 1);
                pn += __shfl_xor_sync(0xFFFFFFFFu, pn, 2);
                an += __shfl_xor_sync(0xFFFFFFFFu, an, 1);
                an += __shfl_xor_sync(0xFFFFFFFFu, an, 2);
                float pinv = 1.f / fmaxf(sqrtf(pn), 1e-12f);
                float ainv = 1.f / fmaxf(sqrtf(an), 1e-12f);

                if (i == 0) {
                    size_t gb = (size_t)blockIdx.x * 32 + b_cta;
                    float* po = out + gb * 64 + q * 2;
                    float* ao = out + (size_t)n_pool_blocks * 64 + gb * 64 + q * 2;
                    #pragma unroll
                    for (int ns = 0; ns < 8; ++ns) {
                        *(float2*)(po + ns * 8) =
                            make_float2(hp[2 * ns] * pinv, hp[2 * ns + 1] * pinv);
                        float2 bv = *(const float2*)(bsm + ns * 8 + q * 2);
                        float x0 = v[2 * ns]     + bv.x;
                        float x1 = v[2 * ns + 1] + bv.y;
                        x0 = (x0 >= 0.f) ? x0 : alpha * x0;
                        x1 = (x1 >= 0.f) ? x1 : alpha * x1;
                        *(float2*)(ao + ns * 8) = make_float2(x0 * ainv, x1 * ainv);
                    }
                }
            }
        }
    }
}

extern "C" void kernel_launch(void* const* d_in, const int* in_sizes, int n_in,
                              void* d_out, int out_size) {
    const float* feat   = (const float*)d_in[0];
    const float* w      = (const float*)d_in[1];
    const float* weight = (const float*)d_in[2];
    const float* bias   = (const float*)d_in[3];
    const float* alpha  = (const float*)d_in[4];
    float* out = (float*)d_out;

    int n_nodes = in_sizes[0] / 128;       // N = 524288
    int n_blk   = n_nodes / 4;             // B = 131072
    int grid    = n_nodes / 128;           // 4096 CTAs (128 rows each, 128 threads)

    prep_weight_kernel<<<32, 256>>>(weight);

    cudaFuncSetAttribute(gcn_f16_kernel,
                         cudaFuncAttributeMaxDynamicSharedMemorySize, SMEM_TOTAL);
    gcn_f16_kernel<<<grid, 128, SMEM_TOTAL>>>(feat, w, bias, alpha, out, n_blk);
}

// round 7
// speedup vs baseline: 1.0369x; 1.0369x over previous
#include <cuda_runtime.h>
#include <cuda_fp16.h>
#include <cstdint>

// ====================== helpers ======================
__device__ __forceinline__ uint32_t smem_u32(const void* p) {
    uint32_t a;
    asm("{ .reg .u64 t; cvta.to.shared.u64 t, %1; cvt.u32.u64 %0, t; }" : "=r"(a) : "l"(p));
    return a;
}
__device__ __forceinline__ void ldsm_x4t(uint32_t* d, uint32_t addr) {
    asm volatile("ldmatrix.sync.aligned.m8n8.x4.trans.shared.b16 {%0,%1,%2,%3}, [%4];"
        : "=r"(d[0]), "=r"(d[1]), "=r"(d[2]), "=r"(d[3]) : "r"(addr));
}
__device__ __forceinline__ void mma_f16(float* c, const uint32_t* a, uint32_t b0, uint32_t b1) {
    asm volatile(
        "mma.sync.aligned.m16n8k16.row.col.f32.f16.f16.f32 "
        "{%0,%1,%2,%3}, {%4,%5,%6,%7}, {%8,%9}, {%0,%1,%2,%3};"
        : "+f"(c[0]), "+f"(c[1]), "+f"(c[2]), "+f"(c[3])
        : "r"(a[0]), "r"(a[1]), "r"(a[2]), "r"(a[3]), "r"(b0), "r"(b1));
}
__device__ __forceinline__ uint32_t h2u(__half2 h) { return *reinterpret_cast<uint32_t*>(&h); }

// ====================== weight prep (once) ======================
// g_Bh: 128 rows (logical mma-k) x 64 fp16, 16B chunks XOR-swizzled by (k&7).
// Row k holds W[perm(k)][*]:  q=k&15, c=(q>>1)&3, e=q&1, hi8=q>>3 -> p = 16*(k>>4)+4c+2*hi8+e
__device__ unsigned char g_Bh[128 * 128];

__global__ void prep_weight_kernel(const float* __restrict__ weight) {
    int i = blockIdx.x * 256 + threadIdx.x;
    if (i < 8192) {
        int k = i >> 6, n = i & 63;
        int ks = k >> 4, q = k & 15;
        int c = (q >> 1) & 3, e = q & 1, hi8 = q >> 3;
        int p = 16 * ks + 4 * c + 2 * hi8 + e;
        __half h = __float2half_rn(weight[p * 64 + n]);
        int chunk = (n >> 3) ^ (k & 7);
        int off = k * 128 + chunk * 16 + (n & 7) * 2;
        *reinterpret_cast<__half*>(g_Bh + off) = h;
    }
}

// ====================== smem layout ======================
#define SM_B    0u
#define SM_W    16384u
#define SM_BIAS 18432u
#define SM_P    18688u          // norm partials: 32 blocks x 2 colg x {pn,an} = 512 B
#define SMEM_TOTAL 19200

__global__ void __launch_bounds__(256, 3) gcn_f16_kernel(
    const float* __restrict__ feat,
    const float* __restrict__ w,
    const float* __restrict__ bias,
    const float* __restrict__ alpha_p,
    float* __restrict__ out,
    int n_pool_blocks)
{
    extern __shared__ unsigned char s_raw[];
    const uint32_t sb = smem_u32(s_raw);
    const int tid = threadIdx.x;
    const int wid = tid >> 5;
    const int lid = tid & 31;
    const int rowg = wid >> 1;          // 0..3 : 32-row group
    const int colg = wid & 1;           // 0..1 : 32-col group

    const float alpha = __ldg(alpha_p);

    // ---------- stage B tile (16KB), edge weights (2KB), bias ----------
    {
        const uint4* gbp = (const uint4*)&g_Bh[0];
        uint4* sp = (uint4*)(s_raw + SM_B);
        #pragma unroll
        for (int i = 0; i < 4; ++i) sp[tid + i * 256] = gbp[tid + i * 256];
        if (tid < 128) ((uint4*)(s_raw + SM_W))[tid] =
            ((const uint4*)(w + (size_t)blockIdx.x * 512))[tid];
        if (tid < 16)  ((uint4*)(s_raw + SM_BIAS))[tid] = ((const uint4*)bias)[tid];
    }
    __syncthreads();

    // ---------- MMA: warp = 32 rows x 32 cols; K = 2x128 (hi/lo + 2 m16 tiles share B) ----------
    float acc[2][4][4];
    #pragma unroll
    for (int mt = 0; mt < 2; ++mt)
        #pragma unroll
        for (int t = 0; t < 4; ++t)
            #pragma unroll
            for (int i = 0; i < 4; ++i) acc[mt][t][i] = 0.f;

    {
        const int c  = lid & 3;
        const int rq = lid >> 2;
        const float* fbase = feat + (size_t)blockIdx.x * (128 * 128)
                           + (size_t)(rowg * 32 + rq) * 128 + 4 * c;

        const int bKrel = (lid & 7) + ((lid >> 3) & 1) * 8;
        const uint32_t bRow = (uint32_t)bKrel * 128u;
        const int bS  = bKrel & 7;
        const int bC0 = (lid >> 4) + (colg << 2);   // chunk = colg*4 + j*2 + (lid>>4)

        #pragma unroll
        for (int ks = 0; ks < 8; ++ks) {
            uint32_t b[8];
            const uint32_t bkb = sb + SM_B + (uint32_t)(ks * 2048) + bRow;
            #pragma unroll
            for (int j = 0; j < 2; ++j)
                ldsm_x4t(b + 4 * j, bkb + (uint32_t)((((j << 1) + bC0) ^ bS) << 4));

            #pragma unroll
            for (int mt = 0; mt < 2; ++mt) {
                float4 F0 = *(const float4*)(fbase + (mt * 16    ) * 128 + 16 * ks);
                float4 F1 = *(const float4*)(fbase + (mt * 16 + 8) * 128 + 16 * ks);

                __half2 H0 = __floats2half2_rn(F0.x, F0.y);
                __half2 H1 = __floats2half2_rn(F1.x, F1.y);
                __half2 H2 = __floats2half2_rn(F0.z, F0.w);
                __half2 H3 = __floats2half2_rn(F1.z, F1.w);
                float2 g0 = __half22float2(H0), g1 = __half22float2(H1);
                float2 g2 = __half22float2(H2), g3 = __half22float2(H3);
                __half2 L0 = __floats2half2_rn(F0.x - g0.x, F0.y - g0.y);
                __half2 L1 = __floats2half2_rn(F1.x - g1.x, F1.y - g1.y);
                __half2 L2 = __floats2half2_rn(F0.z - g2.x, F0.w - g2.y);
                __half2 L3 = __floats2half2_rn(F1.z - g3.x, F1.w - g3.y);
                uint32_t aH[4] = { h2u(H0), h2u(H1), h2u(H2), h2u(H3) };
                uint32_t aL[4] = { h2u(L0), h2u(L1), h2u(L2), h2u(L3) };

                #pragma unroll
                for (int ns = 0; ns < 4; ++ns) {
                    uint32_t b0 = b[(ns >> 1) * 4 + (ns & 1) * 2];
                    uint32_t b1 = b[(ns >> 1) * 4 + (ns & 1) * 2 + 1];
                    mma_f16(acc[mt][ns], aH, b0, b1);
                    mma_f16(acc[mt][ns], aL, b0, b1);
                }
            }
        }
    }

    // ---------- in-register epilogue with cross-warp norm combine ----------
    {
        const float* wsm = (const float*)(s_raw + SM_W);
        const float* bsm = (const float*)(s_raw + SM_BIAS) + colg * 32;
        float* part = (float*)(s_raw + SM_P);
        const int q  = lid & 3;
        const int i  = (lid >> 2) & 3;          // row within node-block
        const int bq = (lid >> 4) & 1;
        const int srcBase = lid & 0x13;         // keep q + bq bits

        #pragma unroll
        for (int mt = 0; mt < 2; ++mt) {
            #pragma unroll
            for (int h = 0; h < 2; ++h) {
                const int b_cta = rowg * 8 + mt * 4 + 2 * h + bq;
                const float* wb = wsm + b_cta * 16;

                float v[8];
                #pragma unroll
                for (int ns = 0; ns < 4; ++ns) {
                    v[2 * ns]     = acc[mt][ns][2 * h];
                    v[2 * ns + 1] = acc[mt][ns][2 * h + 1];
                }

                float hp[8];
                #pragma unroll
                for (int ns = 0; ns < 4; ++ns) {
                    float2 bv = *(const float2*)(bsm + ns * 8 + q * 2);
                    hp[2 * ns] = bv.x; hp[2 * ns + 1] = bv.y;
                }
                #pragma unroll
                for (int s = 1; s <= 3; ++s) {
                    int sl = srcBase | (s << 2);
                    float wsj = wb[s * 4 + i];
                    #pragma unroll
                    for (int c = 0; c < 8; ++c)
                        hp[c] = fmaf(wsj, __shfl_sync(0xFFFFFFFFu, v[c], sl), hp[c]);
                }

                #pragma unroll
                for (int c = 0; c < 8; ++c)
                    hp[c] = (hp[c] >= 0.f) ? hp[c] : alpha * hp[c];
                #pragma unroll
                for (int c = 0; c < 8; ++c) hp[c] += __shfl_xor_sync(0xFFFFFFFFu, hp[c], 4);
                #pragma unroll
                for (int c = 0; c < 8; ++c) hp[c] += __shfl_xor_sync(0xFFFFFFFFu, hp[c], 8);

                float pn = 0.f, an = 0.f;
                #pragma unroll
                for (int c = 0; c < 8; ++c) {
                    float p = hp[c] * 0.25f;
                    hp[c] = p;
                    pn = fmaf(p, p, pn);
                    float2 bv = *(const float2*)(bsm + (c >> 1) * 8 + q * 2);
                    float x = v[c] + ((c & 1) ? bv.y : bv.x);
                    x = (x >= 0.f) ? x : alpha * x;
                    an = fmaf(x, x, an);              // valid on i==0 lanes
                }
                pn += __shfl_xor_sync(0xFFFFFFFFu, pn, 1);
                pn += __shfl_xor_sync(0xFFFFFFFFu, pn, 2);
                an += __shfl_xor_sync(0xFFFFFFFFu, an, 1);
                an += __shfl_xor_sync(0xFFFFFFFFu, an, 2);

                // publish this colg's partial; combine with sibling warp's half
                if ((lid & 15) == 0) {
                    part[b_cta * 4 + colg * 2]     = pn;
                    part[b_cta * 4 + colg * 2 + 1] = an;
                }
                __syncthreads();
                float pnT = part[b_cta * 4] + part[b_cta * 4 + 2];
                float anT = part[b_cta * 4 + 1] + part[b_cta * 4 + 3];
                float pinv = 1.f / fmaxf(sqrtf(pnT), 1e-12f);
                float ainv = 1.f / fmaxf(sqrtf(anT), 1e-12f);

                if (i == 0) {
                    size_t gb = (size_t)blockIdx.x * 32 + b_cta;
                    float* po = out + gb * 64 + colg * 32 + q * 2;
                    float* ao = out + (size_t)n_pool_blocks * 64 + gb * 64 + colg * 32 + q * 2;
                    #pragma unroll
                    for (int ns = 0; ns < 4; ++ns) {
                        *(float2*)(po + ns * 8) =
                            make_float2(hp[2 * ns] * pinv, hp[2 * ns + 1] * pinv);
                        float2 bv = *(const float2*)(bsm + ns * 8 + q * 2);
                        float x0 = v[2 * ns]     + bv.x;
                        float x1 = v[2 * ns + 1] + bv.y;
                        x0 = (x0 >= 0.f) ? x0 : alpha * x0;
                        x1 = (x1 >= 0.f) ? x1 : alpha * x1;
                        *(float2*)(ao + ns * 8) = make_float2(x0 * ainv, x1 * ainv);
                    }
                }
            }
        }
    }
}

extern "C" void kernel_launch(void* const* d_in, const int* in_sizes, int n_in,
                              void* d_out, int out_size) {
    const float* feat   = (const float*)d_in[0];
    const float* w      = (const float*)d_in[1];
    const float* weight = (const float*)d_in[2];
    const float* bias   = (const float*)d_in[3];
    const float* alpha  = (const float*)d_in[4];
    float* out = (float*)d_out;

    int n_nodes = in_sizes[0] / 128;       // N = 524288
    int n_blk   = n_nodes / 4;             // B = 131072
    int grid    = n_nodes / 128;           // 4096 CTAs (128 rows, 256 threads)

    prep_weight_kernel<<<32, 256>>>(weight);

    cudaFuncSetAttribute(gcn_f16_kernel,
                         cudaFuncAttributeMaxDynamicSharedMemorySize, SMEM_TOTAL);
    gcn_f16_kernel<<<grid, 256, SMEM_TOTAL>>>(feat, w, bias, alpha, out, n_blk);
}

// round 8
// speedup vs baseline: 1.1707x; 1.1291x over previous
#include <cuda_runtime.h>
#include <cuda_fp16.h>
#include <cstdint>

// ====================== helpers ======================
__device__ __forceinline__ uint32_t smem_u32(const void* p) {
    uint32_t a;
    asm("{ .reg .u64 t; cvta.to.shared.u64 t, %1; cvt.u32.u64 %0, t; }" : "=r"(a) : "l"(p));
    return a;
}
__device__ __forceinline__ void ldsm_x4t(uint32_t* d, uint32_t addr) {
    asm volatile("ldmatrix.sync.aligned.m8n8.x4.trans.shared.b16 {%0,%1,%2,%3}, [%4];"
        : "=r"(d[0]), "=r"(d[1]), "=r"(d[2]), "=r"(d[3]) : "r"(addr));
}
__device__ __forceinline__ void mma_f16(float* c, const uint32_t* a, uint32_t b0, uint32_t b1) {
    asm volatile(
        "mma.sync.aligned.m16n8k16.row.col.f32.f16.f16.f32 "
        "{%0,%1,%2,%3}, {%4,%5,%6,%7}, {%8,%9}, {%0,%1,%2,%3};"
        : "+f"(c[0]), "+f"(c[1]), "+f"(c[2]), "+f"(c[3])
        : "r"(a[0]), "r"(a[1]), "r"(a[2]), "r"(a[3]), "r"(b0), "r"(b1));
}
__device__ __forceinline__ uint32_t h2u(__half2 h) { return *reinterpret_cast<uint32_t*>(&h); }

// ====================== weight prep (once) ======================
// g_Bh: 128 rows (logical mma-k) x 64 fp16, 16B chunks XOR-swizzled by (k&7).
// Row k holds W[perm(k)][*]:  q=k&15, c=(q>>1)&3, e=q&1, hi8=q>>3 -> p = 16*(k>>4)+4c+2*hi8+e
__device__ unsigned char g_Bh[128 * 128];

__global__ void prep_weight_kernel(const float* __restrict__ weight) {
    int i = blockIdx.x * 256 + threadIdx.x;
    if (i < 8192) {
        int k = i >> 6, n = i & 63;
        int ks = k >> 4, q = k & 15;
        int c = (q >> 1) & 3, e = q & 1, hi8 = q >> 3;
        int p = 16 * ks + 4 * c + 2 * hi8 + e;
        __half h = __float2half_rn(weight[p * 64 + n]);
        int chunk = (n >> 3) ^ (k & 7);
        int off = k * 128 + chunk * 16 + (n & 7) * 2;
        *reinterpret_cast<__half*>(g_Bh + off) = h;
    }
}

// ====================== smem layout ======================
#define SM_B    0u
#define SM_W    16384u
#define SM_BIAS 18432u
#define SMEM_TOTAL 18688

__global__ void __launch_bounds__(128, 4) gcn_f16_kernel(
    const float* __restrict__ feat,
    const float* __restrict__ w,
    const float* __restrict__ bias,
    const float* __restrict__ alpha_p,
    float* __restrict__ out,
    int n_pool_blocks)
{
    extern __shared__ unsigned char s_raw[];
    const uint32_t sb = smem_u32(s_raw);
    const int tid = threadIdx.x;
    const int wid = tid >> 5;
    const int lid = tid & 31;

    const float alpha = __ldg(alpha_p);

    // ---------- stage B tile (16KB), edge weights (2KB), bias ----------
    {
        const uint4* gbp = (const uint4*)&g_Bh[0];
        uint4* sp = (uint4*)(s_raw + SM_B);
        #pragma unroll
        for (int i = 0; i < 8; ++i) sp[tid + i * 128] = gbp[tid + i * 128];
        ((uint4*)(s_raw + SM_W))[tid] =
            ((const uint4*)(w + (size_t)blockIdx.x * 512))[tid];
        if (tid < 16)  ((uint4*)(s_raw + SM_BIAS))[tid] = ((const uint4*)bias)[tid];
    }
    __syncthreads();

    // ---------- MMA: warp = 32 rows x 64 cols, x-hi only (K=128) ----------
    float acc[2][8][4];
    #pragma unroll
    for (int mt = 0; mt < 2; ++mt)
        #pragma unroll
        for (int t = 0; t < 8; ++t)
            #pragma unroll
            for (int i = 0; i < 4; ++i) acc[mt][t][i] = 0.f;

    {
        const int c  = lid & 3;
        const int rq = lid >> 2;
        const float* fbase = feat + (size_t)blockIdx.x * (128 * 128)
                           + (size_t)(wid * 32 + rq) * 128 + 4 * c;

        const int bKrel = (lid & 7) + ((lid >> 3) & 1) * 8;
        const uint32_t bRow = (uint32_t)bKrel * 128u;
        const int bS  = bKrel & 7;
        const int bC0 = lid >> 4;

        #pragma unroll
        for (int ks = 0; ks < 8; ++ks) {
            uint32_t b[16];
            const uint32_t bkb = sb + SM_B + (uint32_t)(ks * 2048) + bRow;
            #pragma unroll
            for (int j = 0; j < 4; ++j)
                ldsm_x4t(b + 4 * j, bkb + (uint32_t)((((j << 1) + bC0) ^ bS) << 4));

            #pragma unroll
            for (int mt = 0; mt < 2; ++mt) {
                float4 F0 = *(const float4*)(fbase + (mt * 16    ) * 128 + 16 * ks);
                float4 F1 = *(const float4*)(fbase + (mt * 16 + 8) * 128 + 16 * ks);

                uint32_t aH[4] = {
                    h2u(__floats2half2_rn(F0.x, F0.y)),
                    h2u(__floats2half2_rn(F1.x, F1.y)),
                    h2u(__floats2half2_rn(F0.z, F0.w)),
                    h2u(__floats2half2_rn(F1.z, F1.w)) };

                #pragma unroll
                for (int ns = 0; ns < 8; ++ns) {
                    uint32_t b0 = b[(ns >> 1) * 4 + (ns & 1) * 2];
                    uint32_t b1 = b[(ns >> 1) * 4 + (ns & 1) * 2 + 1];
                    mma_f16(acc[mt][ns], aH, b0, b1);
                }
            }
        }
    }

    // ---------- in-register epilogue ----------
    {
        const float* wsm = (const float*)(s_raw + SM_W);
        const float* bsm = (const float*)(s_raw + SM_BIAS);
        const int q  = lid & 3;
        const int i  = (lid >> 2) & 3;          // row within node-block
        const int bq = (lid >> 4) & 1;
        const int srcBase = lid & 0x13;         // keep q + bq bits

        #pragma unroll
        for (int mt = 0; mt < 2; ++mt) {
            #pragma unroll
            for (int h = 0; h < 2; ++h) {
                const int b_cta = wid * 8 + mt * 4 + 2 * h + bq;
                const float* wb = wsm + b_cta * 16;

                float v[16];
                #pragma unroll
                for (int ns = 0; ns < 8; ++ns) {
                    v[2 * ns]     = acc[mt][ns][2 * h];
                    v[2 * ns + 1] = acc[mt][ns][2 * h + 1];
                }

                float hp[16];
                #pragma unroll
                for (int ns = 0; ns < 8; ++ns) {
                    float2 bv = *(const float2*)(bsm + ns * 8 + q * 2);
                    hp[2 * ns] = bv.x; hp[2 * ns + 1] = bv.y;
                }
                #pragma unroll
                for (int s = 1; s <= 3; ++s) {
                    int sl = srcBase | (s << 2);
                    float wsj = wb[s * 4 + i];
                    #pragma unroll
                    for (int c = 0; c < 16; ++c)
                        hp[c] = fmaf(wsj, __shfl_sync(0xFFFFFFFFu, v[c], sl), hp[c]);
                }

                #pragma unroll
                for (int c = 0; c < 16; ++c)
                    hp[c] = (hp[c] >= 0.f) ? hp[c] : alpha * hp[c];
                #pragma unroll
                for (int c = 0; c < 16; ++c) hp[c] += __shfl_xor_sync(0xFFFFFFFFu, hp[c], 4);
                #pragma unroll
                for (int c = 0; c < 16; ++c) hp[c] += __shfl_xor_sync(0xFFFFFFFFu, hp[c], 8);

                float pn = 0.f, an = 0.f;
                #pragma unroll
                for (int c = 0; c < 16; ++c) {
                    float p = hp[c] * 0.25f;
                    hp[c] = p;
                    pn = fmaf(p, p, pn);
                    float2 bv = *(const float2*)(bsm + (c >> 1) * 8 + q * 2);
                    float x = v[c] + ((c & 1) ? bv.y : bv.x);
                    x = (x >= 0.f) ? x : alpha * x;
                    an = fmaf(x, x, an);
                }
                pn += __shfl_xor_sync(0xFFFFFFFFu, pn, 1);
                pn += __shfl_xor_sync(0xFFFFFFFFu, pn, 2);
                an += __shfl_xor_sync(0xFFFFFFFFu, an, 1);
                an += __shfl_xor_sync(0xFFFFFFFFu, an, 2);
                float pinv = 1.f / fmaxf(sqrtf(pn), 1e-12f);
                float ainv = 1.f / fmaxf(sqrtf(an), 1e-12f);

                if (i == 0) {
                    size_t gb = (size_t)blockIdx.x * 32 + b_cta;
                    float* po = out + gb * 64 + q * 2;
                    float* ao = out + (size_t)n_pool_blocks * 64 + gb * 64 + q * 2;
                    #pragma unroll
                    for (int ns = 0; ns < 8; ++ns) {
                        *(float2*)(po + ns * 8) =
                            make_float2(hp[2 * ns] * pinv, hp[2 * ns + 1] * pinv);
                        float2 bv = *(const float2*)(bsm + ns * 8 + q * 2);
                        float x0 = v[2 * ns]     + bv.x;
                        float x1 = v[2 * ns + 1] + bv.y;
                        x0 = (x0 >= 0.f) ? x0 : alpha * x0;
                        x1 = (x1 >= 0.f) ? x1 : alpha * x1;
                        *(float2*)(ao + ns * 8) = make_float2(x0 * ainv, x1 * ainv);
                    }
                }
            }
        }
    }
}

extern "C" void kernel_launch(void* const* d_in, const int* in_sizes, int n_in,
                              void* d_out, int out_size) {
    const float* feat   = (const float*)d_in[0];
    const float* w      = (const float*)d_in[1];
    const float* weight = (const float*)d_in[2];
    const float* bias   = (const float*)d_in[3];
    const float* alpha  = (const float*)d_in[4];
    float* out = (float*)d_out;

    int n_nodes = in_sizes[0] / 128;       // N = 524288
    int n_blk   = n_nodes / 4;             // B = 131072
    int grid    = n_nodes / 128;           // 4096 CTAs (128 rows, 128 threads)

    prep_weight_kernel<<<32, 256>>>(weight);

    cudaFuncSetAttribute(gcn_f16_kernel,
                         cudaFuncAttributeMaxDynamicSharedMemorySize, SMEM_TOTAL);
    gcn_f16_kernel<<<grid, 128, SMEM_TOTAL>>>(feat, w, bias, alpha, out, n_blk);
}

// round 10
// speedup vs baseline: 1.5183x; 1.2969x over previous
#include <cuda_runtime.h>
#include <cuda_fp16.h>
#include <cstdint>

// ====================== helpers ======================
__device__ __forceinline__ uint32_t smem_u32(const void* p) {
    uint32_t a;
    asm("{ .reg .u64 t; cvta.to.shared.u64 t, %1; cvt.u32.u64 %0, t; }" : "=r"(a) : "l"(p));
    return a;
}
__device__ __forceinline__ void ldsm_x4t(uint32_t* d, uint32_t addr) {
    asm volatile("ldmatrix.sync.aligned.m8n8.x4.trans.shared.b16 {%0,%1,%2,%3}, [%4];"
        : "=r"(d[0]), "=r"(d[1]), "=r"(d[2]), "=r"(d[3]) : "r"(addr));
}
__device__ __forceinline__ void mma_f16(float* c, const uint32_t* a, uint32_t b0, uint32_t b1) {
    asm volatile(
        "mma.sync.aligned.m16n8k16.row.col.f32.f16.f16.f32 "
        "{%0,%1,%2,%3}, {%4,%5,%6,%7}, {%8,%9}, {%0,%1,%2,%3};"
        : "+f"(c[0]), "+f"(c[1]), "+f"(c[2]), "+f"(c[3])
        : "r"(a[0]), "r"(a[1]), "r"(a[2]), "r"(a[3]), "r"(b0), "r"(b1));
}
__device__ __forceinline__ uint32_t h2u(__half2 h) { return *reinterpret_cast<uint32_t*>(&h); }

// ====================== weight prep (once) ======================
// g_Bh: 128 rows (logical mma-k) x 64 fp16, 16B chunks XOR-swizzled by (k&7).
// Row k holds W[perm(k)][*]:  q=k&15, c=(q>>1)&3, e=q&1, hi8=q>>3 -> p = 16*(k>>4)+4c+2*hi8+e
__device__ unsigned char g_Bh[128 * 128];

__global__ void prep_weight_kernel(const float* __restrict__ weight) {
    int i = blockIdx.x * 256 + threadIdx.x;
    if (i < 8192) {
        int k = i >> 6, n = i & 63;
        int ks = k >> 4, q = k & 15;
        int c = (q >> 1) & 3, e = q & 1, hi8 = q >> 3;
        int p = 16 * ks + 4 * c + 2 * hi8 + e;
        __half h = __float2half_rn(weight[p * 64 + n]);
        int chunk = (n >> 3) ^ (k & 7);
        int off = k * 128 + chunk * 16 + (n & 7) * 2;
        *reinterpret_cast<__half*>(g_Bh + off) = h;
    }
}

// ====================== smem layout ======================
// B tile : 16384 B @ 0 (dead after MMA)
// H      : 128 x 68 fp32 = 34816 B @ 0 (overlays B after barrier)
// w      : 2048 B @ 34816 ; bias : 256 B @ 36864
#define SM_B    0u
#define SM_H    0u
#define SM_W    34816u
#define SM_BIAS 36864u
#define SMEM_TOTAL 37120
#define H_STRIDE 68

__global__ void __launch_bounds__(256, 4) gcn_f16_kernel(
    const float* __restrict__ feat,
    const float* __restrict__ w,
    const float* __restrict__ bias,
    const float* __restrict__ alpha_p,
    float* __restrict__ out,
    int n_pool_blocks)
{
    extern __shared__ unsigned char s_raw[];
    const uint32_t sb = smem_u32(s_raw);
    const int tid = threadIdx.x;
    const int wid = tid >> 5;
    const int lid = tid & 31;

    const float alpha = __ldg(alpha_p);

    // ---------- stage B tile (16KB), edge weights (2KB), bias ----------
    {
        const uint4* gbp = (const uint4*)&g_Bh[0];
        uint4* sp = (uint4*)(s_raw + SM_B);
        #pragma unroll
        for (int i = 0; i < 4; ++i) sp[tid + i * 256] = gbp[tid + i * 256];
        if (tid < 128) ((uint4*)(s_raw + SM_W))[tid] =
            ((const uint4*)(w + (size_t)blockIdx.x * 512))[tid];
        if (tid < 16)  ((uint4*)(s_raw + SM_BIAS))[tid] = ((const uint4*)bias)[tid];
    }
    __syncthreads();

    // ---------- MMA: warp = 16 rows x 64 cols; hi-only (K=128) ----------
    float acc[8][4];
    #pragma unroll
    for (int t = 0; t < 8; ++t)
        #pragma unroll
        for (int i = 0; i < 4; ++i) acc[t][i] = 0.f;

    {
        const int c  = lid & 3;
        const int rq = lid >> 2;
        const float* f0 = feat + (size_t)blockIdx.x * (128 * 128)
                        + (size_t)(wid * 16 + rq) * 128 + 4 * c;
        const float* f1 = f0 + 8 * 128;

        const int bKrel = (lid & 7) + ((lid >> 3) & 1) * 8;
        const uint32_t bRow = (uint32_t)bKrel * 128u;
        const int bS  = bKrel & 7;
        const int bC0 = lid >> 4;

        #pragma unroll
        for (int ks = 0; ks < 8; ++ks) {
            float4 F0 = *(const float4*)(f0 + 16 * ks);
            float4 F1 = *(const float4*)(f1 + 16 * ks);
            uint32_t aH[4] = {
                h2u(__floats2half2_rn(F0.x, F0.y)),
                h2u(__floats2half2_rn(F1.x, F1.y)),
                h2u(__floats2half2_rn(F0.z, F0.w)),
                h2u(__floats2half2_rn(F1.z, F1.w)) };

            const uint32_t bkb = sb + SM_B + (uint32_t)(ks * 2048) + bRow;
            // chunk pair 0: j = 0,1 -> ns 0..3   (pairing: ns=2j -> b[4j],b[4j+1]; ns=2j+1 -> b[4j+2],b[4j+3])
            {
                uint32_t b[8];
                ldsm_x4t(b,     bkb + (uint32_t)(((0 + bC0) ^ bS) << 4));
                ldsm_x4t(b + 4, bkb + (uint32_t)(((2 + bC0) ^ bS) << 4));
                mma_f16(acc[0], aH, b[0], b[1]);
                mma_f16(acc[1], aH, b[2], b[3]);
                mma_f16(acc[2], aH, b[4], b[5]);
                mma_f16(acc[3], aH, b[6], b[7]);
            }
            // chunk pair 1: j = 2,3 -> ns 4..7
            {
                uint32_t b[8];
                ldsm_x4t(b,     bkb + (uint32_t)(((4 + bC0) ^ bS) << 4));
                ldsm_x4t(b + 4, bkb + (uint32_t)(((6 + bC0) ^ bS) << 4));
                mma_f16(acc[4], aH, b[0], b[1]);
                mma_f16(acc[5], aH, b[2], b[3]);
                mma_f16(acc[6], aH, b[4], b[5]);
                mma_f16(acc[7], aH, b[6], b[7]);
            }
        }
    }

    __syncthreads();   // all warps done reading B; safe to overlay H

    // ---------- accumulators -> smem H[128][64] (stride 68) ----------
    {
        float* Hp = (float*)(s_raw + SM_H);
        const int row = wid * 16 + (lid >> 2);
        const int cc  = (lid & 3) << 1;
        #pragma unroll
        for (int ns = 0; ns < 8; ++ns) {
            int col = ns * 8 + cc;
            *(float2*)(Hp + (size_t)row * H_STRIDE + col)       = make_float2(acc[ns][0], acc[ns][1]);
            *(float2*)(Hp + (size_t)(row + 8) * H_STRIDE + col) = make_float2(acc[ns][2], acc[ns][3]);
        }
    }
    __syncthreads();

    // ---------- epilogue: 32 node-blocks x 8 threads (8 cols/thread) ----------
    {
        const int tb = tid >> 3;
        const int q  = tid & 7;
        const int c0 = q << 3;
        const float* Hb = (const float*)(s_raw + SM_H);
        const float* ws = (const float*)(s_raw + SM_W) + tb * 16;
        const float* bs = (const float*)(s_raw + SM_BIAS);

        float a0[8], h1[8], h2[8], h3[8], bb[8];
        const float* r0p = Hb + (size_t)(4 * tb    ) * H_STRIDE + c0;
        const float* r1p = Hb + (size_t)(4 * tb + 1) * H_STRIDE + c0;
        const float* r2p = Hb + (size_t)(4 * tb + 2) * H_STRIDE + c0;
        const float* r3p = Hb + (size_t)(4 * tb + 3) * H_STRIDE + c0;
        *(float4*)(a0) = *(const float4*)(r0p); *(float4*)(a0 + 4) = *(const float4*)(r0p + 4);
        *(float4*)(h1) = *(const float4*)(r1p); *(float4*)(h1 + 4) = *(const float4*)(r1p + 4);
        *(float4*)(h2) = *(const float4*)(r2p); *(float4*)(h2 + 4) = *(const float4*)(r2p + 4);
        *(float4*)(h3) = *(const float4*)(r3p); *(float4*)(h3 + 4) = *(const float4*)(r3p + 4);
        *(float4*)(bb) = *(const float4*)(bs + c0); *(float4*)(bb + 4) = *(const float4*)(bs + c0 + 4);

        float pool[8];
        #pragma unroll
        for (int cc = 0; cc < 8; ++cc) pool[cc] = 0.f;
        #pragma unroll
        for (int j = 0; j < 4; ++j) {
            float w1 = ws[4 + j], w2 = ws[8 + j], w3 = ws[12 + j];
            #pragma unroll
            for (int cc = 0; cc < 8; ++cc) {
                float hv = fmaf(w1, h1[cc], fmaf(w2, h2[cc], w3 * h3[cc])) + bb[cc];
                hv = (hv >= 0.f) ? hv : alpha * hv;
                pool[cc] += hv;
            }
        }
        float pn = 0.f, an = 0.f;
        float aa[8];
        #pragma unroll
        for (int cc = 0; cc < 8; ++cc) {
            pool[cc] *= 0.25f;
            pn = fmaf(pool[cc], pool[cc], pn);
            float x = a0[cc] + bb[cc];
            x = (x >= 0.f) ? x : alpha * x;
            aa[cc] = x;
            an = fmaf(x, x, an);
        }
        #pragma unroll
        for (int o = 1; o < 8; o <<= 1) {
            pn += __shfl_xor_sync(0xFFFFFFFFu, pn, o);
            an += __shfl_xor_sync(0xFFFFFFFFu, an, o);
        }
        float pinv = 1.f / fmaxf(sqrtf(pn), 1e-12f);
        float ainv = 1.f / fmaxf(sqrtf(an), 1e-12f);

        size_t gb = (size_t)blockIdx.x * 32 + tb;
        float* po = out + gb * 64 + c0;
        float* ao = out + (size_t)n_pool_blocks * 64 + gb * 64 + c0;
        *(float4*)(po)     = make_float4(pool[0]*pinv, pool[1]*pinv, pool[2]*pinv, pool[3]*pinv);
        *(float4*)(po + 4) = make_float4(pool[4]*pinv, pool[5]*pinv, pool[6]*pinv, pool[7]*pinv);
        *(float4*)(ao)     = make_float4(aa[0]*ainv, aa[1]*ainv, aa[2]*ainv, aa[3]*ainv);
        *(float4*)(ao + 4) = make_float4(aa[4]*ainv, aa[5]*ainv, aa[6]*ainv, aa[7]*ainv);
    }
}

extern "C" void kernel_launch(void* const* d_in, const int* in_sizes, int n_in,
                              void* d_out, int out_size) {
    const float* feat   = (const float*)d_in[0];
    const float* w      = (const float*)d_in[1];
    const float* weight = (const float*)d_in[2];
    const float* bias   = (const float*)d_in[3];
    const float* alpha  = (const float*)d_in[4];
    float* out = (float*)d_out;

    int n_nodes = in_sizes[0] / 128;       // N = 524288
    int n_blk   = n_nodes / 4;             // B = 131072
    int grid    = n_nodes / 128;           // 4096 CTAs

    prep_weight_kernel<<<32, 256>>>(weight);

    cudaFuncSetAttribute(gcn_f16_kernel,
                         cudaFuncAttributeMaxDynamicSharedMemorySize, SMEM_TOTAL);
    gcn_f16_kernel<<<grid, 256, SMEM_TOTAL>>>(feat, w, bias, alpha, out, n_blk);
}

// round 11
// speedup vs baseline: 1.6423x; 1.0817x over previous
#include <cuda_runtime.h>
#include <cuda_fp16.h>
#include <cstdint>

// ====================== helpers ======================
__device__ __forceinline__ uint32_t smem_u32(const void* p) {
    uint32_t a;
    asm("{ .reg .u64 t; cvta.to.shared.u64 t, %1; cvt.u32.u64 %0, t; }" : "=r"(a) : "l"(p));
    return a;
}
__device__ __forceinline__ void ldsm_x4t(uint32_t* d, uint32_t addr) {
    asm volatile("ldmatrix.sync.aligned.m8n8.x4.trans.shared.b16 {%0,%1,%2,%3}, [%4];"
        : "=r"(d[0]), "=r"(d[1]), "=r"(d[2]), "=r"(d[3]) : "r"(addr));
}
__device__ __forceinline__ void mma_f16(float* c, const uint32_t* a, uint32_t b0, uint32_t b1) {
    asm volatile(
        "mma.sync.aligned.m16n8k16.row.col.f32.f16.f16.f32 "
        "{%0,%1,%2,%3}, {%4,%5,%6,%7}, {%8,%9}, {%0,%1,%2,%3};"
        : "+f"(c[0]), "+f"(c[1]), "+f"(c[2]), "+f"(c[3])
        : "r"(a[0]), "r"(a[1]), "r"(a[2]), "r"(a[3]), "r"(b0), "r"(b1));
}
__device__ __forceinline__ uint32_t h2u(__half2 h) { return *reinterpret_cast<uint32_t*>(&h); }

// ====================== weight prep (once) ======================
// g_Bh: 128 rows (logical mma-k) x 64 fp16, 16B chunks XOR-swizzled by (k&7).
// Row k holds W[perm(k)][*]:  q=k&15, c=(q>>1)&3, e=q&1, hi8=q>>3 -> p = 16*(k>>4)+4c+2*hi8+e
__device__ unsigned char g_Bh[128 * 128];

__global__ void prep_weight_kernel(const float* __restrict__ weight) {
    int i = blockIdx.x * 256 + threadIdx.x;
    if (i < 8192) {
        int k = i >> 6, n = i & 63;
        int ks = k >> 4, q = k & 15;
        int c = (q >> 1) & 3, e = q & 1, hi8 = q >> 3;
        int p = 16 * ks + 4 * c + 2 * hi8 + e;
        __half h = __float2half_rn(weight[p * 64 + n]);
        int chunk = (n >> 3) ^ (k & 7);
        int off = k * 128 + chunk * 16 + (n & 7) * 2;
        *reinterpret_cast<__half*>(g_Bh + off) = h;
    }
}

// ====================== smem layout ======================
// B tile : 16384 B @ 0 (dead after MMA)
// H      : 128 rows x (72-word stride, skewed) fp32 = 36864 B @ 0 (overlays B)
// w      : 2048 B @ 36864 ; bias : 256 B @ 38912
#define SM_B    0u
#define SM_H    0u
#define SM_W    36864u
#define SM_BIAS 38912u
#define SMEM_TOTAL 39168
#define H_STRIDE 72
// word offset inside H: row*72 + col + ((col>>5)<<2)  (bank-conflict-free both ways)

__global__ void __launch_bounds__(256, 4) gcn_f16_kernel(
    const float* __restrict__ feat,
    const float* __restrict__ w,
    const float* __restrict__ bias,
    const float* __restrict__ alpha_p,
    float* __restrict__ out,
    int n_pool_blocks)
{
    extern __shared__ unsigned char s_raw[];
    const uint32_t sb = smem_u32(s_raw);
    const int tid = threadIdx.x;
    const int wid = tid >> 5;
    const int lid = tid & 31;

    const float alpha = __ldg(alpha_p);

    // ---------- stage B tile (16KB), edge weights (2KB), bias ----------
    {
        const uint4* gbp = (const uint4*)&g_Bh[0];
        uint4* sp = (uint4*)(s_raw + SM_B);
        #pragma unroll
        for (int i = 0; i < 4; ++i) sp[tid + i * 256] = gbp[tid + i * 256];
        if (tid < 128) ((uint4*)(s_raw + SM_W))[tid] =
            ((const uint4*)(w + (size_t)blockIdx.x * 512))[tid];
        if (tid < 16)  ((uint4*)(s_raw + SM_BIAS))[tid] = ((const uint4*)bias)[tid];
    }
    __syncthreads();

    // ---------- MMA: warp = 16 rows x 64 cols; hi-only (K=128) ----------
    float acc[8][4];
    #pragma unroll
    for (int t = 0; t < 8; ++t)
        #pragma unroll
        for (int i = 0; i < 4; ++i) acc[t][i] = 0.f;

    {
        const int c  = lid & 3;
        const int rq = lid >> 2;
        const float* f0 = feat + (size_t)blockIdx.x * (128 * 128)
                        + (size_t)(wid * 16 + rq) * 128 + 4 * c;
        const float* f1 = f0 + 8 * 128;

        const int bKrel = (lid & 7) + ((lid >> 3) & 1) * 8;
        const uint32_t bRow = (uint32_t)bKrel * 128u;
        const int bS  = bKrel & 7;
        const int bC0 = lid >> 4;

        #pragma unroll
        for (int ks = 0; ks < 8; ++ks) {
            float4 F0 = *(const float4*)(f0 + 16 * ks);
            float4 F1 = *(const float4*)(f1 + 16 * ks);
            uint32_t aH[4] = {
                h2u(__floats2half2_rn(F0.x, F0.y)),
                h2u(__floats2half2_rn(F1.x, F1.y)),
                h2u(__floats2half2_rn(F0.z, F0.w)),
                h2u(__floats2half2_rn(F1.z, F1.w)) };

            const uint32_t bkb = sb + SM_B + (uint32_t)(ks * 2048) + bRow;
            {
                uint32_t b[8];
                ldsm_x4t(b,     bkb + (uint32_t)(((0 + bC0) ^ bS) << 4));
                ldsm_x4t(b + 4, bkb + (uint32_t)(((2 + bC0) ^ bS) << 4));
                mma_f16(acc[0], aH, b[0], b[1]);
                mma_f16(acc[1], aH, b[2], b[3]);
                mma_f16(acc[2], aH, b[4], b[5]);
                mma_f16(acc[3], aH, b[6], b[7]);
            }
            {
                uint32_t b[8];
                ldsm_x4t(b,     bkb + (uint32_t)(((4 + bC0) ^ bS) << 4));
                ldsm_x4t(b + 4, bkb + (uint32_t)(((6 + bC0) ^ bS) << 4));
                mma_f16(acc[4], aH, b[0], b[1]);
                mma_f16(acc[5], aH, b[2], b[3]);
                mma_f16(acc[6], aH, b[4], b[5]);
                mma_f16(acc[7], aH, b[6], b[7]);
            }
        }
    }

    __syncthreads();   // all warps done reading B; safe to overlay H

    // ---------- accumulators -> smem H (stride 72 + skew, conflict-free) ----------
    {
        float* Hp = (float*)(s_raw + SM_H);
        const int row = wid * 16 + (lid >> 2);
        const int cc  = (lid & 3) << 1;
        #pragma unroll
        for (int ns = 0; ns < 8; ++ns) {
            int col  = ns * 8 + cc;
            int skew = (ns >> 2) << 2;                   // ((col>>5)<<2)
            *(float2*)(Hp + (size_t)row * H_STRIDE + col + skew)
                = make_float2(acc[ns][0], acc[ns][1]);
            *(float2*)(Hp + (size_t)(row + 8) * H_STRIDE + col + skew)
                = make_float2(acc[ns][2], acc[ns][3]);
        }
    }
    __syncthreads();

    // ---------- epilogue: 32 node-blocks x 8 threads (8 cols/thread) ----------
    {
        const int tb = tid >> 3;
        const int q  = tid & 7;
        const int c0 = q << 3;
        const int skew = (c0 >> 5) << 2;
        const float* Hb = (const float*)(s_raw + SM_H) + c0 + skew;
        const float* ws = (const float*)(s_raw + SM_W) + tb * 16;
        const float* bs = (const float*)(s_raw + SM_BIAS);

        float a0[8], h1[8], h2[8], h3[8], bb[8];
        const float* r0p = Hb + (size_t)(4 * tb    ) * H_STRIDE;
        const float* r1p = Hb + (size_t)(4 * tb + 1) * H_STRIDE;
        const float* r2p = Hb + (size_t)(4 * tb + 2) * H_STRIDE;
        const float* r3p = Hb + (size_t)(4 * tb + 3) * H_STRIDE;
        *(float4*)(a0) = *(const float4*)(r0p); *(float4*)(a0 + 4) = *(const float4*)(r0p + 4);
        *(float4*)(h1) = *(const float4*)(r1p); *(float4*)(h1 + 4) = *(const float4*)(r1p + 4);
        *(float4*)(h2) = *(const float4*)(r2p); *(float4*)(h2 + 4) = *(const float4*)(r2p + 4);
        *(float4*)(h3) = *(const float4*)(r3p); *(float4*)(h3 + 4) = *(const float4*)(r3p + 4);
        *(float4*)(bb) = *(const float4*)(bs + c0); *(float4*)(bb + 4) = *(const float4*)(bs + c0 + 4);

        float pool[8];
        #pragma unroll
        for (int cc = 0; cc < 8; ++cc) pool[cc] = 0.f;
        #pragma unroll
        for (int j = 0; j < 4; ++j) {
            float w1 = ws[4 + j], w2 = ws[8 + j], w3 = ws[12 + j];
            #pragma unroll
            for (int cc = 0; cc < 8; ++cc) {
                float hv = fmaf(w1, h1[cc], fmaf(w2, h2[cc], w3 * h3[cc])) + bb[cc];
                hv = (hv >= 0.f) ? hv : alpha * hv;
                pool[cc] += hv;
            }
        }
        float pn = 0.f, an = 0.f;
        float aa[8];
        #pragma unroll
        for (int cc = 0; cc < 8; ++cc) {
            pool[cc] *= 0.25f;
            pn = fmaf(pool[cc], pool[cc], pn);
            float x = a0[cc] + bb[cc];
            x = (x >= 0.f) ? x : alpha * x;
            aa[cc] = x;
            an = fmaf(x, x, an);
        }
        #pragma unroll
        for (int o = 1; o < 8; o <<= 1) {
            pn += __shfl_xor_sync(0xFFFFFFFFu, pn, o);
            an += __shfl_xor_sync(0xFFFFFFFFu, an, o);
        }
        float pinv = 1.f / fmaxf(sqrtf(pn), 1e-12f);
        float ainv = 1.f / fmaxf(sqrtf(an), 1e-12f);

        size_t gb = (size_t)blockIdx.x * 32 + tb;
        float* po = out + gb * 64 + c0;
        float* ao = out + (size_t)n_pool_blocks * 64 + gb * 64 + c0;
        *(float4*)(po)     = make_float4(pool[0]*pinv, pool[1]*pinv, pool[2]*pinv, pool[3]*pinv);
        *(float4*)(po + 4) = make_float4(pool[4]*pinv, pool[5]*pinv, pool[6]*pinv, pool[7]*pinv);
        *(float4*)(ao)     = make_float4(aa[0]*ainv, aa[1]*ainv, aa[2]*ainv, aa[3]*ainv);
        *(float4*)(ao + 4) = make_float4(aa[4]*ainv, aa[5]*ainv, aa[6]*ainv, aa[7]*ainv);
    }
}

extern "C" void kernel_launch(void* const* d_in, const int* in_sizes, int n_in,
                              void* d_out, int out_size) {
    const float* feat   = (const float*)d_in[0];
    const float* w      = (const float*)d_in[1];
    const float* weight = (const float*)d_in[2];
    const float* bias   = (const float*)d_in[3];
    const float* alpha  = (const float*)d_in[4];
    float* out = (float*)d_out;

    int n_nodes = in_sizes[0] / 128;       // N = 524288
    int n_blk   = n_nodes / 4;             // B = 131072
    int grid    = n_nodes / 128;           // 4096 CTAs

    prep_weight_kernel<<<32, 256>>>(weight);

    cudaFuncSetAttribute(gcn_f16_kernel,
                         cudaFuncAttributeMaxDynamicSharedMemorySize, SMEM_TOTAL);
    gcn_f16_kernel<<<grid, 256, SMEM_TOTAL>>>(feat, w, bias, alpha, out, n_blk);
}

// round 12
// speedup vs baseline: 1.6854x; 1.0262x over previous
#include <cuda_runtime.h>
#include <cuda_fp16.h>
#include <cstdint>

// ====================== helpers ======================
__device__ __forceinline__ uint32_t smem_u32(const void* p) {
    uint32_t a;
    asm("{ .reg .u64 t; cvta.to.shared.u64 t, %1; cvt.u32.u64 %0, t; }" : "=r"(a) : "l"(p));
    return a;
}
__device__ __forceinline__ void ldsm_x4t(uint32_t* d, uint32_t addr) {
    asm volatile("ldmatrix.sync.aligned.m8n8.x4.trans.shared.b16 {%0,%1,%2,%3}, [%4];"
        : "=r"(d[0]), "=r"(d[1]), "=r"(d[2]), "=r"(d[3]) : "r"(addr));
}
__device__ __forceinline__ void mma_f16(float* c, const uint32_t* a, uint32_t b0, uint32_t b1) {
    asm volatile(
        "mma.sync.aligned.m16n8k16.row.col.f32.f16.f16.f32 "
        "{%0,%1,%2,%3}, {%4,%5,%6,%7}, {%8,%9}, {%0,%1,%2,%3};"
        : "+f"(c[0]), "+f"(c[1]), "+f"(c[2]), "+f"(c[3])
        : "r"(a[0]), "r"(a[1]), "r"(a[2]), "r"(a[3]), "r"(b0), "r"(b1));
}
__device__ __forceinline__ uint32_t h2u(__half2 h) { return *reinterpret_cast<uint32_t*>(&h); }

// ====================== weight prep (once) ======================
// g_Bh: 128 rows (logical mma-k) x 64 fp16, 16B chunks XOR-swizzled by (k&7).
// Row k holds W[perm(k)][*]:  q=k&15, c=(q>>1)&3, e=q&1, hi8=q>>3 -> p = 16*(k>>4)+4c+2*hi8+e
__device__ unsigned char g_Bh[128 * 128];

__global__ void prep_weight_kernel(const float* __restrict__ weight) {
    int i = blockIdx.x * 256 + threadIdx.x;
    if (i < 8192) {
        int k = i >> 6, n = i & 63;
        int ks = k >> 4, q = k & 15;
        int c = (q >> 1) & 3, e = q & 1, hi8 = q >> 3;
        int p = 16 * ks + 4 * c + 2 * hi8 + e;
        __half h = __float2half_rn(weight[p * 64 + n]);
        int chunk = (n >> 3) ^ (k & 7);
        int off = k * 128 + chunk * 16 + (n & 7) * 2;
        *reinterpret_cast<__half*>(g_Bh + off) = h;
    }
}

// ====================== smem layout ======================
// B tile : 16384 B @ 0 (dead after MMA)
// H      : 128 rows x 72 fp16 (stride 72 halves) = 18432 B @ 0 (overlays B)
// w      : 2048 B @ 18432 ; bias : 256 B @ 20480
#define SM_B    0u
#define SM_H    0u
#define SM_W    18432u
#define SM_BIAS 20480u
#define SMEM_TOTAL 20736
#define H_STRIDE 72   // in halves; 36 words -> conflict-free STS.32 and LDS.128

__global__ void __launch_bounds__(256, 4) gcn_f16_kernel(
    const float* __restrict__ feat,
    const float* __restrict__ w,
    const float* __restrict__ bias,
    const float* __restrict__ alpha_p,
    float* __restrict__ out,
    int n_pool_blocks)
{
    extern __shared__ unsigned char s_raw[];
    const uint32_t sb = smem_u32(s_raw);
    const int tid = threadIdx.x;
    const int wid = tid >> 5;
    const int lid = tid & 31;

    const float alpha = __ldg(alpha_p);

    // ---------- stage B tile (16KB), edge weights (2KB), bias ----------
    {
        const uint4* gbp = (const uint4*)&g_Bh[0];
        uint4* sp = (uint4*)(s_raw + SM_B);
        #pragma unroll
        for (int i = 0; i < 4; ++i) sp[tid + i * 256] = gbp[tid + i * 256];
        if (tid < 128) ((uint4*)(s_raw + SM_W))[tid] =
            ((const uint4*)(w + (size_t)blockIdx.x * 512))[tid];
        if (tid < 16)  ((uint4*)(s_raw + SM_BIAS))[tid] = ((const uint4*)bias)[tid];
    }
    __syncthreads();

    // ---------- MMA: warp = 16 rows x 64 cols; hi-only (K=128) ----------
    float acc[8][4];
    #pragma unroll
    for (int t = 0; t < 8; ++t)
        #pragma unroll
        for (int i = 0; i < 4; ++i) acc[t][i] = 0.f;

    {
        const int c  = lid & 3;
        const int rq = lid >> 2;
        const float* f0 = feat + (size_t)blockIdx.x * (128 * 128)
                        + (size_t)(wid * 16 + rq) * 128 + 4 * c;
        const float* f1 = f0 + 8 * 128;

        const int bKrel = (lid & 7) + ((lid >> 3) & 1) * 8;
        const uint32_t bRow = (uint32_t)bKrel * 128u;
        const int bS  = bKrel & 7;
        const int bC0 = lid >> 4;

        #pragma unroll
        for (int ks = 0; ks < 8; ++ks) {
            float4 F0 = *(const float4*)(f0 + 16 * ks);
            float4 F1 = *(const float4*)(f1 + 16 * ks);
            uint32_t aH[4] = {
                h2u(__floats2half2_rn(F0.x, F0.y)),
                h2u(__floats2half2_rn(F1.x, F1.y)),
                h2u(__floats2half2_rn(F0.z, F0.w)),
                h2u(__floats2half2_rn(F1.z, F1.w)) };

            const uint32_t bkb = sb + SM_B + (uint32_t)(ks * 2048) + bRow;
            {
                uint32_t b[8];
                ldsm_x4t(b,     bkb + (uint32_t)(((0 + bC0) ^ bS) << 4));
                ldsm_x4t(b + 4, bkb + (uint32_t)(((2 + bC0) ^ bS) << 4));
                mma_f16(acc[0], aH, b[0], b[1]);
                mma_f16(acc[1], aH, b[2], b[3]);
                mma_f16(acc[2], aH, b[4], b[5]);
                mma_f16(acc[3], aH, b[6], b[7]);
            }
            {
                uint32_t b[8];
                ldsm_x4t(b,     bkb + (uint32_t)(((4 + bC0) ^ bS) << 4));
                ldsm_x4t(b + 4, bkb + (uint32_t)(((6 + bC0) ^ bS) << 4));
                mma_f16(acc[4], aH, b[0], b[1]);
                mma_f16(acc[5], aH, b[2], b[3]);
                mma_f16(acc[6], aH, b[4], b[5]);
                mma_f16(acc[7], aH, b[6], b[7]);
            }
        }
    }

    __syncthreads();   // all warps done reading B; safe to overlay H

    // ---------- accumulators -> smem H[128][64] fp16 (stride 72 halves) ----------
    {
        __half* Hp = (__half*)(s_raw + SM_H);
        const int row = wid * 16 + (lid >> 2);
        const int cc  = (lid & 3) << 1;
        #pragma unroll
        for (int ns = 0; ns < 8; ++ns) {
            int col = ns * 8 + cc;
            *(__half2*)(Hp + (size_t)row * H_STRIDE + col)
                = __floats2half2_rn(acc[ns][0], acc[ns][1]);
            *(__half2*)(Hp + (size_t)(row + 8) * H_STRIDE + col)
                = __floats2half2_rn(acc[ns][2], acc[ns][3]);
        }
    }
    __syncthreads();

    // ---------- epilogue: 32 node-blocks x 8 threads (8 cols/thread) ----------
    {
        const int tb = tid >> 3;
        const int q  = tid & 7;
        const int c0 = q << 3;
        const __half* Hb = (const __half*)(s_raw + SM_H) + c0;
        const float* ws = (const float*)(s_raw + SM_W) + tb * 16;
        const float* bs = (const float*)(s_raw + SM_BIAS);

        float a0[8], h1[8], h2[8], h3[8], bb[8];
        #define LOADH(dst, rowidx) do {                                          \
            uint4 _u = *(const uint4*)(Hb + (size_t)(rowidx) * H_STRIDE);        \
            const __half2* _hh = (const __half2*)&_u;                            \
            _Pragma("unroll")                                                    \
            for (int _j = 0; _j < 4; ++_j) {                                     \
                float2 _f = __half22float2(_hh[_j]);                             \
                (dst)[2 * _j] = _f.x; (dst)[2 * _j + 1] = _f.y;                  \
            } } while (0)
        LOADH(a0, 4 * tb);
        LOADH(h1, 4 * tb + 1);
        LOADH(h2, 4 * tb + 2);
        LOADH(h3, 4 * tb + 3);
        #undef LOADH
        *(float4*)(bb) = *(const float4*)(bs + c0); *(float4*)(bb + 4) = *(const float4*)(bs + c0 + 4);

        float pool[8];
        #pragma unroll
        for (int cc = 0; cc < 8; ++cc) pool[cc] = 0.f;
        #pragma unroll
        for (int j = 0; j < 4; ++j) {
            float w1 = ws[4 + j], w2 = ws[8 + j], w3 = ws[12 + j];
            #pragma unroll
            for (int cc = 0; cc < 8; ++cc) {
                float hv = fmaf(w1, h1[cc], fmaf(w2, h2[cc], w3 * h3[cc])) + bb[cc];
                hv = (hv >= 0.f) ? hv : alpha * hv;
                pool[cc] += hv;
            }
        }
        float pn = 0.f, an = 0.f;
        float aa[8];
        #pragma unroll
        for (int cc = 0; cc < 8; ++cc) {
            pool[cc] *= 0.25f;
            pn = fmaf(pool[cc], pool[cc], pn);
            float x = a0[cc] + bb[cc];
            x = (x >= 0.f) ? x : alpha * x;
            aa[cc] = x;
            an = fmaf(x, x, an);
        }
        #pragma unroll
        for (int o = 1; o < 8; o <<= 1) {
            pn += __shfl_xor_sync(0xFFFFFFFFu, pn, o);
            an += __shfl_xor_sync(0xFFFFFFFFu, an, o);
        }
        float pinv = 1.f / fmaxf(sqrtf(pn), 1e-12f);
        float ainv = 1.f / fmaxf(sqrtf(an), 1e-12f);

        size_t gb = (size_t)blockIdx.x * 32 + tb;
        float* po = out + gb * 64 + c0;
        float* ao = out + (size_t)n_pool_blocks * 64 + gb * 64 + c0;
        *(float4*)(po)     = make_float4(pool[0]*pinv, pool[1]*pinv, pool[2]*pinv, pool[3]*pinv);
        *(float4*)(po + 4) = make_float4(pool[4]*pinv, pool[5]*pinv, pool[6]*pinv, pool[7]*pinv);
        *(float4*)(ao)     = make_float4(aa[0]*ainv, aa[1]*ainv, aa[2]*ainv, aa[3]*ainv);
        *(float4*)(ao + 4) = make_float4(aa[4]*ainv, aa[5]*ainv, aa[6]*ainv, aa[7]*ainv);
    }
}

extern "C" void kernel_launch(void* const* d_in, const int* in_sizes, int n_in,
                              void* d_out, int out_size) {
    const float* feat   = (const float*)d_in[0];
    const float* w      = (const float*)d_in[1];
    const float* weight = (const float*)d_in[2];
    const float* bias   = (const float*)d_in[3];
    const float* alpha  = (const float*)d_in[4];
    float* out = (float*)d_out;

    int n_nodes = in_sizes[0] / 128;       // N = 524288
    int n_blk   = n_nodes / 4;             // B = 131072
    int grid    = n_nodes / 128;           // 4096 CTAs

    prep_weight_kernel<<<32, 256>>>(weight);

    cudaFuncSetAttribute(gcn_f16_kernel,
                         cudaFuncAttributeMaxDynamicSharedMemorySize, SMEM_TOTAL);
    gcn_f16_kernel<<<grid, 256, SMEM_TOTAL>>>(feat, w, bias, alpha, out, n_blk);
}

// round 13
// speedup vs baseline: 1.7561x; 1.0420x over previous
#include <cuda_runtime.h>
#include <cuda_fp16.h>
#include <cstdint>

// ====================== helpers ======================
__device__ __forceinline__ uint32_t smem_u32(const void* p) {
    uint32_t a;
    asm("{ .reg .u64 t; cvta.to.shared.u64 t, %1; cvt.u32.u64 %0, t; }" : "=r"(a) : "l"(p));
    return a;
}
__device__ __forceinline__ void ldsm_x4t(uint32_t* d, uint32_t addr) {
    asm volatile("ldmatrix.sync.aligned.m8n8.x4.trans.shared.b16 {%0,%1,%2,%3}, [%4];"
        : "=r"(d[0]), "=r"(d[1]), "=r"(d[2]), "=r"(d[3]) : "r"(addr));
}
__device__ __forceinline__ void mma_f16(float* c, const uint32_t* a, uint32_t b0, uint32_t b1) {
    asm volatile(
        "mma.sync.aligned.m16n8k16.row.col.f32.f16.f16.f32 "
        "{%0,%1,%2,%3}, {%4,%5,%6,%7}, {%8,%9}, {%0,%1,%2,%3};"
        : "+f"(c[0]), "+f"(c[1]), "+f"(c[2]), "+f"(c[3])
        : "r"(a[0]), "r"(a[1]), "r"(a[2]), "r"(a[3]), "r"(b0), "r"(b1));
}
__device__ __forceinline__ uint32_t h2u(__half2 h) { return *reinterpret_cast<uint32_t*>(&h); }

// ====================== weight prep (once) ======================
// g_Bh: 128 rows (logical mma-k) x 64 fp16, 16B chunks XOR-swizzled by (k&7).
// Row k holds W[perm(k)][*]:  q=k&15, c=(q>>1)&3, e=q&1, hi8=q>>3 -> p = 16*(k>>4)+4c+2*hi8+e
__device__ unsigned char g_Bh[128 * 128];

__global__ void prep_weight_kernel(const float* __restrict__ weight) {
    int i = blockIdx.x * 256 + threadIdx.x;
    if (i < 8192) {
        int k = i >> 6, n = i & 63;
        int ks = k >> 4, q = k & 15;
        int c = (q >> 1) & 3, e = q & 1, hi8 = q >> 3;
        int p = 16 * ks + 4 * c + 2 * hi8 + e;
        __half h = __float2half_rn(weight[p * 64 + n]);
        int chunk = (n >> 3) ^ (k & 7);
        int off = k * 128 + chunk * 16 + (n & 7) * 2;
        *reinterpret_cast<__half*>(g_Bh + off) = h;
    }
}

// ====================== smem layout (no overlay; persistent CTA) ======================
// B   : 16384 B @ 0          (staged ONCE per CTA)
// H   : 128 x 72 fp16 = 18432 B @ 16384
// w   : 2048 B @ 34816 (per tile)
// bias: 256 B @ 36864  (staged once)
#define SM_B    0u
#define SM_H    16384u
#define SM_W    34816u
#define SM_BIAS 36864u
#define SMEM_TOTAL 37120
#define H_STRIDE 72   // halves; conflict-free STS.32 and LDS.128

__global__ void __launch_bounds__(256, 4) gcn_f16_kernel(
    const float* __restrict__ feat,
    const float* __restrict__ w,
    const float* __restrict__ bias,
    const float* __restrict__ alpha_p,
    float* __restrict__ out,
    int n_pool_blocks,
    int n_tiles)
{
    extern __shared__ unsigned char s_raw[];
    const uint32_t sb = smem_u32(s_raw);
    const int tid = threadIdx.x;
    const int wid = tid >> 5;
    const int lid = tid & 31;

    const float alpha = __ldg(alpha_p);

    // ---------- stage B tile (16KB) + bias ONCE ----------
    {
        const uint4* gbp = (const uint4*)&g_Bh[0];
        uint4* sp = (uint4*)(s_raw + SM_B);
        #pragma unroll
        for (int i = 0; i < 4; ++i) sp[tid + i * 256] = gbp[tid + i * 256];
        if (tid < 16) ((uint4*)(s_raw + SM_BIAS))[tid] = ((const uint4*)bias)[tid];
    }

    // ---------- per-lane invariants ----------
    const int c  = lid & 3;
    const int rq = lid >> 2;
    const int bKrel = (lid & 7) + ((lid >> 3) & 1) * 8;
    const uint32_t bRow = (uint32_t)bKrel * 128u;
    const int bS  = bKrel & 7;
    const int bC0 = lid >> 4;

    for (int tile = blockIdx.x; tile < n_tiles; tile += gridDim.x) {
        __syncthreads();   // staging visible (iter 0) / prev epilogue done (iter >0)

        // ---------- per-tile edge weights (2KB) ----------
        if (tid < 128) ((uint4*)(s_raw + SM_W))[tid] =
            ((const uint4*)(w + (size_t)tile * 512))[tid];

        // ---------- MMA: warp = 16 rows x 64 cols; hi-only (K=128) ----------
        float acc[8][4];
        #pragma unroll
        for (int t = 0; t < 8; ++t)
            #pragma unroll
            for (int i = 0; i < 4; ++i) acc[t][i] = 0.f;

        {
            const float* f0 = feat + (size_t)tile * (128 * 128)
                            + (size_t)(wid * 16 + rq) * 128 + 4 * c;
            const float* f1 = f0 + 8 * 128;

            #pragma unroll
            for (int ks = 0; ks < 8; ++ks) {
                float4 F0 = *(const float4*)(f0 + 16 * ks);
                float4 F1 = *(const float4*)(f1 + 16 * ks);
                uint32_t aH[4] = {
                    h2u(__floats2half2_rn(F0.x, F0.y)),
                    h2u(__floats2half2_rn(F1.x, F1.y)),
                    h2u(__floats2half2_rn(F0.z, F0.w)),
                    h2u(__floats2half2_rn(F1.z, F1.w)) };

                const uint32_t bkb = sb + SM_B + (uint32_t)(ks * 2048) + bRow;
                {
                    uint32_t b[8];
                    ldsm_x4t(b,     bkb + (uint32_t)(((0 + bC0) ^ bS) << 4));
                    ldsm_x4t(b + 4, bkb + (uint32_t)(((2 + bC0) ^ bS) << 4));
                    mma_f16(acc[0], aH, b[0], b[1]);
                    mma_f16(acc[1], aH, b[2], b[3]);
                    mma_f16(acc[2], aH, b[4], b[5]);
                    mma_f16(acc[3], aH, b[6], b[7]);
                }
                {
                    uint32_t b[8];
                    ldsm_x4t(b,     bkb + (uint32_t)(((4 + bC0) ^ bS) << 4));
                    ldsm_x4t(b + 4, bkb + (uint32_t)(((6 + bC0) ^ bS) << 4));
                    mma_f16(acc[4], aH, b[0], b[1]);
                    mma_f16(acc[5], aH, b[2], b[3]);
                    mma_f16(acc[6], aH, b[4], b[5]);
                    mma_f16(acc[7], aH, b[6], b[7]);
                }
            }
        }

        // ---------- accumulators -> smem H[128][64] fp16 (stride 72 halves) ----------
        {
            __half* Hp = (__half*)(s_raw + SM_H);
            const int row = wid * 16 + (lid >> 2);
            const int cc  = (lid & 3) << 1;
            #pragma unroll
            for (int ns = 0; ns < 8; ++ns) {
                int col = ns * 8 + cc;
                *(__half2*)(Hp + (size_t)row * H_STRIDE + col)
                    = __floats2half2_rn(acc[ns][0], acc[ns][1]);
                *(__half2*)(Hp + (size_t)(row + 8) * H_STRIDE + col)
                    = __floats2half2_rn(acc[ns][2], acc[ns][3]);
            }
        }
        __syncthreads();   // H + w visible to epilogue

        // ---------- epilogue: 32 node-blocks x 8 threads (8 cols/thread) ----------
        {
            const int tb = tid >> 3;
            const int q  = tid & 7;
            const int c0 = q << 3;
            const __half* Hb = (const __half*)(s_raw + SM_H) + c0;
            const float* ws = (const float*)(s_raw + SM_W) + tb * 16;
            const float* bs = (const float*)(s_raw + SM_BIAS);

            float a0[8], h1[8], h2[8], h3[8], bb[8];
            #define LOADH(dst, rowidx) do {                                          \
                uint4 _u = *(const uint4*)(Hb + (size_t)(rowidx) * H_STRIDE);        \
                const __half2* _hh = (const __half2*)&_u;                            \
                _Pragma("unroll")                                                    \
                for (int _j = 0; _j < 4; ++_j) {                                     \
                    float2 _f = __half22float2(_hh[_j]);                             \
                    (dst)[2 * _j] = _f.x; (dst)[2 * _j + 1] = _f.y;                  \
                } } while (0)
            LOADH(a0, 4 * tb);
            LOADH(h1, 4 * tb + 1);
            LOADH(h2, 4 * tb + 2);
            LOADH(h3, 4 * tb + 3);
            #undef LOADH
            *(float4*)(bb) = *(const float4*)(bs + c0);
            *(float4*)(bb + 4) = *(const float4*)(bs + c0 + 4);

            float pool[8];
            #pragma unroll
            for (int cc = 0; cc < 8; ++cc) pool[cc] = 0.f;
            #pragma unroll
            for (int j = 0; j < 4; ++j) {
                float w1 = ws[4 + j], w2 = ws[8 + j], w3 = ws[12 + j];
                #pragma unroll
                for (int cc = 0; cc < 8; ++cc) {
                    float hv = fmaf(w1, h1[cc], fmaf(w2, h2[cc], w3 * h3[cc])) + bb[cc];
                    hv = (hv >= 0.f) ? hv : alpha * hv;
                    pool[cc] += hv;
                }
            }
            float pn = 0.f, an = 0.f;
            float aa[8];
            #pragma unroll
            for (int cc = 0; cc < 8; ++cc) {
                pool[cc] *= 0.25f;
                pn = fmaf(pool[cc], pool[cc], pn);
                float x = a0[cc] + bb[cc];
                x = (x >= 0.f) ? x : alpha * x;
                aa[cc] = x;
                an = fmaf(x, x, an);
            }
            #pragma unroll
            for (int o = 1; o < 8; o <<= 1) {
                pn += __shfl_xor_sync(0xFFFFFFFFu, pn, o);
                an += __shfl_xor_sync(0xFFFFFFFFu, an, o);
            }
            float pinv = 1.f / fmaxf(sqrtf(pn), 1e-12f);
            float ainv = 1.f / fmaxf(sqrtf(an), 1e-12f);

            size_t gb = (size_t)tile * 32 + tb;
            float* po = out + gb * 64 + c0;
            float* ao = out + (size_t)n_pool_blocks * 64 + gb * 64 + c0;
            *(float4*)(po)     = make_float4(pool[0]*pinv, pool[1]*pinv, pool[2]*pinv, pool[3]*pinv);
            *(float4*)(po + 4) = make_float4(pool[4]*pinv, pool[5]*pinv, pool[6]*pinv, pool[7]*pinv);
            *(float4*)(ao)     = make_float4(aa[0]*ainv, aa[1]*ainv, aa[2]*ainv, aa[3]*ainv);
            *(float4*)(ao + 4) = make_float4(aa[4]*ainv, aa[5]*ainv, aa[6]*ainv, aa[7]*ainv);
        }
    }
}

extern "C" void kernel_launch(void* const* d_in, const int* in_sizes, int n_in,
                              void* d_out, int out_size) {
    const float* feat   = (const float*)d_in[0];
    const float* w      = (const float*)d_in[1];
    const float* weight = (const float*)d_in[2];
    const float* bias   = (const float*)d_in[3];
    const float* alpha  = (const float*)d_in[4];
    float* out = (float*)d_out;

    int n_nodes = in_sizes[0] / 128;       // N = 524288
    int n_blk   = n_nodes / 4;             // B = 131072
    int n_tiles = n_nodes / 128;           // 4096 tiles

    int sms = 148;
    cudaDeviceGetAttribute(&sms, cudaDevAttrMultiProcessorCount, 0);
    int grid = sms * 4;                    // persistent: 4 CTAs/SM
    if (grid > n_tiles) grid = n_tiles;

    prep_weight_kernel<<<32, 256>>>(weight);

    cudaFuncSetAttribute(gcn_f16_kernel,
                         cudaFuncAttributeMaxDynamicSharedMemorySize, SMEM_TOTAL);
    gcn_f16_kernel<<<grid, 256, SMEM_TOTAL>>>(feat, w, bias, alpha, out, n_blk, n_tiles);
}